// round 6
// baseline (speedup 1.0000x reference)
#include <cuda_runtime.h>
#include <cuda_fp16.h>
#include <cstdint>

#define DIN     4096
#define RANK    64
#define MTOT    8192
#define NR      512
#define HCOLS   1536
#define DOUT    4096
#define OUTCOLS 12288

// fp16 staging buffers (device globals; no runtime allocation allowed)
__device__ __align__(16) __half g_Xh[(size_t)MTOT * DIN];    // 64 MB
__device__ __align__(16) __half g_Ah[(size_t)HCOLS * DIN];   // 12.5 MB  [j][k]
__device__ __align__(16) __half g_Bh[(size_t)3 * DOUT * NR]; // 12.5 MB  [comp][n][k]
__device__ __align__(16) __half g_Hh[(size_t)MTOT * HCOLS];  // 25 MB    [m][j]

// ---------------------------------------------------------------------------
// PTX helpers
// ---------------------------------------------------------------------------
__device__ __forceinline__ uint32_t s2u(const void* p) {
    uint32_t a;
    asm("{ .reg .u64 t; cvta.to.shared.u64 t, %1; cvt.u32.u64 %0, t; }" : "=r"(a) : "l"(p));
    return a;
}
__device__ __forceinline__ void cpasync16(uint32_t dst, const void* src) {
    asm volatile("cp.async.cg.shared.global [%0], [%1], 16;" :: "r"(dst), "l"(src) : "memory");
}
#define CP_COMMIT()  asm volatile("cp.async.commit_group;" ::: "memory")
#define CP_WAIT(n)   asm volatile("cp.async.wait_group %0;" :: "n"(n) : "memory")

__device__ __forceinline__ void ldsm4(uint32_t* r, uint32_t a) {
    asm volatile("ldmatrix.sync.aligned.m8n8.x4.shared.b16 {%0,%1,%2,%3}, [%4];"
                 : "=r"(r[0]), "=r"(r[1]), "=r"(r[2]), "=r"(r[3]) : "r"(a));
}
__device__ __forceinline__ void mma16816(float* c, const uint32_t* a, const uint32_t* b) {
    asm volatile(
        "mma.sync.aligned.m16n8k16.row.col.f32.f16.f16.f32 "
        "{%0,%1,%2,%3},{%4,%5,%6,%7},{%8,%9},{%0,%1,%2,%3};"
        : "+f"(c[0]), "+f"(c[1]), "+f"(c[2]), "+f"(c[3])
        : "r"(a[0]), "r"(a[1]), "r"(a[2]), "r"(a[3]), "r"(b[0]), "r"(b[1]));
}
// smem tile row = 64 halves = 128B = 8 chunks of 16B; swizzle chunk ^= row&7
__device__ __forceinline__ uint32_t swz(int row, int chunk) {
    return (uint32_t)(row * 8 + (chunk ^ (row & 7))) * 16u;
}

// ---------------------------------------------------------------------------
// Prep kernels: fp32 -> fp16 convert / transpose
// ---------------------------------------------------------------------------
__global__ void convx_k(const float* __restrict__ x) {
    size_t i = ((size_t)blockIdx.x * 512 + threadIdx.x) * 8;
    float4 a = *(const float4*)(x + i);
    float4 b = *(const float4*)(x + i + 4);
    __half2 h[4];
    h[0] = __floats2half2_rn(a.x, a.y);
    h[1] = __floats2half2_rn(a.z, a.w);
    h[2] = __floats2half2_rn(b.x, b.y);
    h[3] = __floats2half2_rn(b.z, b.w);
    *(uint4*)(g_Xh + i) = *(uint4*)h;
}

__global__ void transA_k(const float* __restrict__ qA, const float* __restrict__ kA,
                         const float* __restrict__ vA) {
    __shared__ float t[32][33];
    int z = blockIdx.z, comp = z >> 3, n = z & 7;
    const float* src = (comp == 0 ? qA : (comp == 1 ? kA : vA)) + (size_t)n * DIN * RANK;
    int i0 = blockIdx.x * 32, r0 = blockIdx.y * 32;
    int tx = threadIdx.x, ty = threadIdx.y;
    #pragma unroll
    for (int q = 0; q < 4; q++)
        t[ty + q * 8][tx] = src[(size_t)(i0 + ty + q * 8) * RANK + r0 + tx];
    __syncthreads();
    size_t jb = (size_t)(comp * 512 + n * 64 + r0);
    #pragma unroll
    for (int q = 0; q < 4; q++)
        g_Ah[(jb + ty + q * 8) * DIN + i0 + tx] = __float2half_rn(t[tx][ty + q * 8]);
}

__global__ void transB_k(const float* __restrict__ qB, const float* __restrict__ kB,
                         const float* __restrict__ vB) {
    __shared__ float t[32][33];
    int comp = blockIdx.z;
    const float* src = (comp == 0 ? qB : (comp == 1 ? kB : vB));  // [512][4096]
    int k0 = blockIdx.x * 32, n0 = blockIdx.y * 32;
    int tx = threadIdx.x, ty = threadIdx.y;
    #pragma unroll
    for (int q = 0; q < 4; q++)
        t[ty + q * 8][tx] = src[(size_t)(k0 + ty + q * 8) * DOUT + n0 + tx];
    __syncthreads();
    __half* dst = g_Bh + (size_t)comp * DOUT * NR;
    #pragma unroll
    for (int q = 0; q < 4; q++)
        dst[(size_t)(n0 + ty + q * 8) * NR + k0 + tx] = __float2half_rn(t[tx][ty + q * 8]);
}

// ---------------------------------------------------------------------------
// GEMM core: C[128m x 256n] += A[128 x K] * B[256 x K]^T   (both K-major fp16)
// 256 threads = 8 warps (2m x 4n), warp tile m64 x n64 (acc 128 regs),
// BK=64, 4-stage cp.async (48KB/stage), register double-buffered fragments:
// LDSM for ks+1 issue under the 32 HMMAs of ks -> latency fully hidden.
// 1 CTA/SM, ~212 regs/thread.
// ---------------------------------------------------------------------------
constexpr int STAGE_B = 48 * 1024;   // 16KB A + 32KB B
constexpr int BSTAGES = 4;

template <int NT>
__device__ __forceinline__ void gemm_core(const __half* Ag, int lda,   // in halves
                                          const __half* Bg, int ldb,
                                          char* sm, float acc[4][8][4]) {
    const int tid  = threadIdx.x;
    const int lane = tid & 31;
    const int wid  = tid >> 5;
    const int wm   = wid & 1;    // 0..1  (m offset 64)
    const int wn   = wid >> 1;   // 0..3  (n offset 64)
    uint32_t smu = s2u(sm);

    auto issue = [&](int t) {
        const int slot = t & (BSTAGES - 1);
        const uint32_t sa = smu + slot * STAGE_B;
        const uint32_t sb = sa + 16384;
        const char* agb = (const char*)Ag + (size_t)t * 128;   // t*64 halves
        const char* bgb = (const char*)Bg + (size_t)t * 128;
        #pragma unroll
        for (int i = 0; i < 4; i++) {                 // A: 1024 chunks / 256 thr
            int lin = tid + 256 * i;
            int row = lin >> 3, c = lin & 7;
            cpasync16(sa + swz(row, c), agb + (size_t)row * lda * 2 + c * 16);
        }
        #pragma unroll
        for (int i = 0; i < 8; i++) {                 // B: 2048 chunks
            int lin = tid + 256 * i;
            int row = lin >> 3, c = lin & 7;
            cpasync16(sb + swz(row, c), bgb + (size_t)row * ldb * 2 + c * 16);
        }
        CP_COMMIT();
    };

    issue(0); issue(1); issue(2);

    uint32_t afb[2][4][4], bfb[2][4][4];

    #pragma unroll 1
    for (int t = 0; t < NT; t++) {
        if (t == NT - 1) { CP_WAIT(0); } else { CP_WAIT(2); }
        __syncthreads();
        if (t + 3 < NT) issue(t + 3);

        const int slot = t & (BSTAGES - 1);
        const uint32_t sa = smu + slot * STAGE_B;
        const uint32_t sb = sa + 16384;

        // preload ks=0 fragments
        #pragma unroll
        for (int mt = 0; mt < 4; mt++)
            ldsm4(afb[0][mt], sa + swz(wm * 64 + mt * 16 + (lane & 15), (lane >> 4)));
        #pragma unroll
        for (int ng = 0; ng < 4; ng++)
            ldsm4(bfb[0][ng], sb + swz(wn * 64 + ng * 16 + (lane & 7) + ((lane >> 4) << 3),
                                       ((lane >> 3) & 1)));

        #pragma unroll
        for (int ks = 0; ks < 4; ks++) {
            const int cur = ks & 1, nxt = cur ^ 1;
            if (ks < 3) {   // prefetch next k-subtile's fragments under the MMAs
                #pragma unroll
                for (int mt = 0; mt < 4; mt++)
                    ldsm4(afb[nxt][mt],
                          sa + swz(wm * 64 + mt * 16 + (lane & 15), (ks + 1) * 2 + (lane >> 4)));
                #pragma unroll
                for (int ng = 0; ng < 4; ng++)
                    ldsm4(bfb[nxt][ng],
                          sb + swz(wn * 64 + ng * 16 + (lane & 7) + ((lane >> 4) << 3),
                                   (ks + 1) * 2 + ((lane >> 3) & 1)));
            }
            #pragma unroll
            for (int mt = 0; mt < 4; mt++)
                #pragma unroll
                for (int ng = 0; ng < 4; ng++) {
                    mma16816(acc[mt][ng * 2 + 0], afb[cur][mt], &bfb[cur][ng][0]);
                    mma16816(acc[mt][ng * 2 + 1], afb[cur][mt], &bfb[cur][ng][2]);
                }
        }
    }
}

// ---------------------------------------------------------------------------
// GEMM1: H[8192,1536] = Xh @ Ah^T, epilogue *= coef (scalar per 64-col block)
// Persistent CTAs over 64x6 = 384 tiles (col-fastest for L2 reuse of X rows).
// ---------------------------------------------------------------------------
__global__ void __launch_bounds__(256, 1)
tc_gemm1(const float* __restrict__ masks, const float* __restrict__ scaling) {
    extern __shared__ __align__(16) char sm[];
    const int tid = threadIdx.x, lane = tid & 31, wid = tid >> 5;
    const int wm = wid & 1, wn = wid >> 1;
    const int NCT = HCOLS / 256;           // 6
    const int NTILE = NCT * (MTOT / 128);  // 384

    #pragma unroll 1
    for (int tile = blockIdx.x; tile < NTILE; tile += gridDim.x) {
        const int row0 = (tile / NCT) * 128;
        const int col0 = (tile % NCT) * 256;

        float acc[4][8][4];
        #pragma unroll
        for (int i = 0; i < 4; i++)
            #pragma unroll
            for (int j = 0; j < 8; j++)
                #pragma unroll
                for (int q = 0; q < 4; q++) acc[i][j][q] = 0.f;

        gemm_core<DIN / 64>(g_Xh + (size_t)row0 * DIN, DIN,
                            g_Ah + (size_t)col0 * DIN, DIN, sm, acc);

        const int nad = ((col0 + wn * 64) >> 6) & 7;
        const int b   = row0 >> 11;
        const float coef = scaling[nad] * masks[nad * 4 + b];

        #pragma unroll
        for (int mt = 0; mt < 4; mt++) {
            #pragma unroll
            for (int ni = 0; ni < 8; ni++) {
                int r = row0 + wm * 64 + mt * 16 + (lane >> 2);
                int c = col0 + wn * 64 + ni * 8 + 2 * (lane & 3);
                *(__half2*)(g_Hh + (size_t)r * HCOLS + c) =
                    __floats2half2_rn(acc[mt][ni][0] * coef, acc[mt][ni][1] * coef);
                *(__half2*)(g_Hh + (size_t)(r + 8) * HCOLS + c) =
                    __floats2half2_rn(acc[mt][ni][2] * coef, acc[mt][ni][3] * coef);
            }
        }
    }
}

// ---------------------------------------------------------------------------
// GEMM2: out[8192,12288]; per comp: out = Hh_comp @ Bh_comp^T
// Persistent CTAs over 64x48 = 3072 tiles.
// ---------------------------------------------------------------------------
__global__ void __launch_bounds__(256, 1)
tc_gemm2(float* __restrict__ out) {
    extern __shared__ __align__(16) char sm[];
    const int tid = threadIdx.x, lane = tid & 31, wid = tid >> 5;
    const int wm = wid & 1, wn = wid >> 1;
    const int NCT = OUTCOLS / 256;         // 48
    const int NTILE = NCT * (MTOT / 128);  // 3072

    #pragma unroll 1
    for (int tile = blockIdx.x; tile < NTILE; tile += gridDim.x) {
        const int row0 = (tile / NCT) * 128;
        const int col0 = (tile % NCT) * 256;
        const int comp = col0 >> 12;
        const int cl   = col0 & 4095;

        float acc[4][8][4];
        #pragma unroll
        for (int i = 0; i < 4; i++)
            #pragma unroll
            for (int j = 0; j < 8; j++)
                #pragma unroll
                for (int q = 0; q < 4; q++) acc[i][j][q] = 0.f;

        gemm_core<NR / 64>(g_Hh + (size_t)row0 * HCOLS + comp * NR, HCOLS,
                           g_Bh + (size_t)comp * DOUT * NR + (size_t)cl * NR, NR, sm, acc);

        #pragma unroll
        for (int mt = 0; mt < 4; mt++) {
            #pragma unroll
            for (int ni = 0; ni < 8; ni++) {
                int r = row0 + wm * 64 + mt * 16 + (lane >> 2);
                int c = col0 + wn * 64 + ni * 8 + 2 * (lane & 3);
                *(float2*)(out + (size_t)r * OUTCOLS + c) =
                    make_float2(acc[mt][ni][0], acc[mt][ni][1]);
                *(float2*)(out + (size_t)(r + 8) * OUTCOLS + c) =
                    make_float2(acc[mt][ni][2], acc[mt][ni][3]);
            }
        }
    }
}

// ---------------------------------------------------------------------------
extern "C" void kernel_launch(void* const* d_in, const int* in_sizes, int n_in,
                              void* d_out, int out_size) {
    const float* x       = (const float*)d_in[0];
    const float* masks   = (const float*)d_in[2];
    const float* scaling = (const float*)d_in[3];
    const float* qA      = (const float*)d_in[4];
    const float* qB      = (const float*)d_in[5];
    const float* kA      = (const float*)d_in[6];
    const float* kB      = (const float*)d_in[7];
    const float* vA      = (const float*)d_in[8];
    const float* vB      = (const float*)d_in[9];
    float* out = (float*)d_out;

    const int SMEM = BSTAGES * STAGE_B;   // 196608 -> 1 CTA/SM
    cudaFuncSetAttribute(tc_gemm1, cudaFuncAttributeMaxDynamicSharedMemorySize, SMEM);
    cudaFuncSetAttribute(tc_gemm2, cudaFuncAttributeMaxDynamicSharedMemorySize, SMEM);

    convx_k<<<(MTOT * DIN) / (512 * 8), 512>>>(x);
    transA_k<<<dim3(DIN / 32, RANK / 32, 24), dim3(32, 8)>>>(qA, kA, vA);
    transB_k<<<dim3(NR / 32, DOUT / 32, 3), dim3(32, 8)>>>(qB, kB, vB);

    const int GRID = 148;   // persistent, 1 CTA per SM
    tc_gemm1<<<GRID, 256, SMEM>>>(masks, scaling);
    tc_gemm2<<<GRID, 256, SMEM>>>(out);
}

// round 7
// speedup vs baseline: 1.0541x; 1.0541x over previous
#include <cuda_runtime.h>
#include <cuda_fp16.h>
#include <cstdint>

#define DIN     4096
#define RANK    64
#define MTOT    8192
#define NR      512
#define HCOLS   1536
#define DOUT    4096
#define OUTCOLS 12288

// fp16 staging buffers (device globals; no runtime allocation allowed)
__device__ __align__(16) __half g_Xh[(size_t)MTOT * DIN];    // 64 MB
__device__ __align__(16) __half g_Ah[(size_t)HCOLS * DIN];   // 12.5 MB  [j][k]
__device__ __align__(16) __half g_Bh[(size_t)3 * DOUT * NR]; // 12.5 MB  [comp][n][k]
__device__ __align__(16) __half g_Hh[(size_t)MTOT * HCOLS];  // 25 MB    [m][j]

// ---------------------------------------------------------------------------
// PTX helpers
// ---------------------------------------------------------------------------
__device__ __forceinline__ uint32_t s2u(const void* p) {
    uint32_t a;
    asm("{ .reg .u64 t; cvta.to.shared.u64 t, %1; cvt.u32.u64 %0, t; }" : "=r"(a) : "l"(p));
    return a;
}
__device__ __forceinline__ void cpasync16(uint32_t dst, const void* src) {
    asm volatile("cp.async.cg.shared.global [%0], [%1], 16;" :: "r"(dst), "l"(src) : "memory");
}
#define CP_COMMIT()  asm volatile("cp.async.commit_group;" ::: "memory")
#define CP_WAIT(n)   asm volatile("cp.async.wait_group %0;" :: "n"(n) : "memory")

__device__ __forceinline__ void ldsm4(uint32_t* r, uint32_t a) {
    asm volatile("ldmatrix.sync.aligned.m8n8.x4.shared.b16 {%0,%1,%2,%3}, [%4];"
                 : "=r"(r[0]), "=r"(r[1]), "=r"(r[2]), "=r"(r[3]) : "r"(a));
}
__device__ __forceinline__ void mma16816(float* c, const uint32_t* a, const uint32_t* b) {
    asm volatile(
        "mma.sync.aligned.m16n8k16.row.col.f32.f16.f16.f32 "
        "{%0,%1,%2,%3},{%4,%5,%6,%7},{%8,%9},{%0,%1,%2,%3};"
        : "+f"(c[0]), "+f"(c[1]), "+f"(c[2]), "+f"(c[3])
        : "r"(a[0]), "r"(a[1]), "r"(a[2]), "r"(a[3]), "r"(b[0]), "r"(b[1]));
}
// smem tile row = 64 halves = 128B = 8 chunks of 16B; swizzle chunk ^= row&7
__device__ __forceinline__ uint32_t swz(int row, int chunk) {
    return (uint32_t)(row * 8 + (chunk ^ (row & 7))) * 16u;
}

// ---------------------------------------------------------------------------
// Prep kernels: fp32 -> fp16 convert / transpose
// ---------------------------------------------------------------------------
__global__ void convx_k(const float* __restrict__ x) {
    size_t i = ((size_t)blockIdx.x * 512 + threadIdx.x) * 8;
    float4 a = *(const float4*)(x + i);
    float4 b = *(const float4*)(x + i + 4);
    __half2 h[4];
    h[0] = __floats2half2_rn(a.x, a.y);
    h[1] = __floats2half2_rn(a.z, a.w);
    h[2] = __floats2half2_rn(b.x, b.y);
    h[3] = __floats2half2_rn(b.z, b.w);
    *(uint4*)(g_Xh + i) = *(uint4*)h;
}

__global__ void transA_k(const float* __restrict__ qA, const float* __restrict__ kA,
                         const float* __restrict__ vA) {
    __shared__ float t[32][33];
    int z = blockIdx.z, comp = z >> 3, n = z & 7;
    const float* src = (comp == 0 ? qA : (comp == 1 ? kA : vA)) + (size_t)n * DIN * RANK;
    int i0 = blockIdx.x * 32, r0 = blockIdx.y * 32;
    int tx = threadIdx.x, ty = threadIdx.y;
    #pragma unroll
    for (int q = 0; q < 4; q++)
        t[ty + q * 8][tx] = src[(size_t)(i0 + ty + q * 8) * RANK + r0 + tx];
    __syncthreads();
    size_t jb = (size_t)(comp * 512 + n * 64 + r0);
    #pragma unroll
    for (int q = 0; q < 4; q++)
        g_Ah[(jb + ty + q * 8) * DIN + i0 + tx] = __float2half_rn(t[tx][ty + q * 8]);
}

__global__ void transB_k(const float* __restrict__ qB, const float* __restrict__ kB,
                         const float* __restrict__ vB) {
    __shared__ float t[32][33];
    int comp = blockIdx.z;
    const float* src = (comp == 0 ? qB : (comp == 1 ? kB : vB));  // [512][4096]
    int k0 = blockIdx.x * 32, n0 = blockIdx.y * 32;
    int tx = threadIdx.x, ty = threadIdx.y;
    #pragma unroll
    for (int q = 0; q < 4; q++)
        t[ty + q * 8][tx] = src[(size_t)(k0 + ty + q * 8) * DOUT + n0 + tx];
    __syncthreads();
    __half* dst = g_Bh + (size_t)comp * DOUT * NR;
    #pragma unroll
    for (int q = 0; q < 4; q++)
        dst[(size_t)(n0 + ty + q * 8) * NR + k0 + tx] = __float2half_rn(t[tx][ty + q * 8]);
}

// ---------------------------------------------------------------------------
// GEMM core: C[128m x 128n] += A[128 x K] * B[128 x K]^T   (both K-major fp16)
// 128 threads = 4 warps (2m x 2n), warp tile m64 x n64 (acc 128 regs),
// BK=64, 3-stage cp.async (32KB/stage), register double-buffered fragments.
// 2 CTAs/SM: sibling CTA's warps fill this CTA's barrier/preload bubbles.
// ---------------------------------------------------------------------------
constexpr int STAGE_B = 32 * 1024;   // 16KB A + 16KB B
constexpr int BSTAGES = 3;

template <int NT>
__device__ __forceinline__ void gemm_core(const __half* Ag, int lda,   // in halves
                                          const __half* Bg, int ldb,
                                          char* sm, float acc[4][8][4]) {
    const int tid  = threadIdx.x;
    const int lane = tid & 31;
    const int wid  = tid >> 5;
    const int wm   = wid & 1;    // 0..1  (m offset 64)
    const int wn   = wid >> 1;   // 0..1  (n offset 64)
    uint32_t smu = s2u(sm);

    auto issue = [&](int t) {
        const int slot = t % BSTAGES;
        const uint32_t sa = smu + slot * STAGE_B;
        const uint32_t sb = sa + 16384;
        const char* agb = (const char*)Ag + (size_t)t * 128;   // t*64 halves
        const char* bgb = (const char*)Bg + (size_t)t * 128;
        #pragma unroll
        for (int i = 0; i < 8; i++) {                 // A: 1024 chunks / 128 thr
            int lin = tid + 128 * i;
            int row = lin >> 3, c = lin & 7;
            cpasync16(sa + swz(row, c), agb + (size_t)row * lda * 2 + c * 16);
        }
        #pragma unroll
        for (int i = 0; i < 8; i++) {                 // B: 1024 chunks
            int lin = tid + 128 * i;
            int row = lin >> 3, c = lin & 7;
            cpasync16(sb + swz(row, c), bgb + (size_t)row * ldb * 2 + c * 16);
        }
        CP_COMMIT();
    };

    issue(0); issue(1);

    uint32_t afb[2][4][4], bfb[2][4][4];

    #pragma unroll 1
    for (int t = 0; t < NT; t++) {
        if (t == NT - 1) { CP_WAIT(0); } else { CP_WAIT(1); }
        __syncthreads();
        if (t + 2 < NT) issue(t + 2);

        const int slot = t % BSTAGES;
        const uint32_t sa = smu + slot * STAGE_B;
        const uint32_t sb = sa + 16384;

        // preload ks=0 fragments
        #pragma unroll
        for (int mt = 0; mt < 4; mt++)
            ldsm4(afb[0][mt], sa + swz(wm * 64 + mt * 16 + (lane & 15), (lane >> 4)));
        #pragma unroll
        for (int ng = 0; ng < 4; ng++)
            ldsm4(bfb[0][ng], sb + swz(wn * 64 + ng * 16 + (lane & 7) + ((lane >> 4) << 3),
                                       ((lane >> 3) & 1)));

        #pragma unroll
        for (int ks = 0; ks < 4; ks++) {
            const int cur = ks & 1, nxt = cur ^ 1;
            if (ks < 3) {   // prefetch next k-subtile's fragments under the MMAs
                #pragma unroll
                for (int mt = 0; mt < 4; mt++)
                    ldsm4(afb[nxt][mt],
                          sa + swz(wm * 64 + mt * 16 + (lane & 15), (ks + 1) * 2 + (lane >> 4)));
                #pragma unroll
                for (int ng = 0; ng < 4; ng++)
                    ldsm4(bfb[nxt][ng],
                          sb + swz(wn * 64 + ng * 16 + (lane & 7) + ((lane >> 4) << 3),
                                   (ks + 1) * 2 + ((lane >> 3) & 1)));
            }
            #pragma unroll
            for (int mt = 0; mt < 4; mt++)
                #pragma unroll
                for (int ng = 0; ng < 4; ng++) {
                    mma16816(acc[mt][ng * 2 + 0], afb[cur][mt], &bfb[cur][ng][0]);
                    mma16816(acc[mt][ng * 2 + 1], afb[cur][mt], &bfb[cur][ng][2]);
                }
        }
    }
}

// ---------------------------------------------------------------------------
// GEMM1: H[8192,1536] = Xh @ Ah^T, epilogue *= coef (scalar per 64-col block)
// Persistent CTAs over 64x12 = 768 tiles (col-fastest for L2 reuse of X rows).
// ---------------------------------------------------------------------------
__global__ void __launch_bounds__(128, 2)
tc_gemm1(const float* __restrict__ masks, const float* __restrict__ scaling) {
    extern __shared__ __align__(16) char sm[];
    const int tid = threadIdx.x, lane = tid & 31, wid = tid >> 5;
    const int wm = wid & 1, wn = wid >> 1;
    const int NCT = HCOLS / 128;           // 12
    const int NTILE = NCT * (MTOT / 128);  // 768

    #pragma unroll 1
    for (int tile = blockIdx.x; tile < NTILE; tile += gridDim.x) {
        const int row0 = (tile / NCT) * 128;
        const int col0 = (tile % NCT) * 128;

        float acc[4][8][4];
        #pragma unroll
        for (int i = 0; i < 4; i++)
            #pragma unroll
            for (int j = 0; j < 8; j++)
                #pragma unroll
                for (int q = 0; q < 4; q++) acc[i][j][q] = 0.f;

        gemm_core<DIN / 64>(g_Xh + (size_t)row0 * DIN, DIN,
                            g_Ah + (size_t)col0 * DIN, DIN, sm, acc);
        __syncthreads();   // protect smem slot 0 from next tile's issue(0)

        const int nad = ((col0 + wn * 64) >> 6) & 7;
        const int b   = row0 >> 11;
        const float coef = scaling[nad] * masks[nad * 4 + b];

        #pragma unroll
        for (int mt = 0; mt < 4; mt++) {
            #pragma unroll
            for (int ni = 0; ni < 8; ni++) {
                int r = row0 + wm * 64 + mt * 16 + (lane >> 2);
                int c = col0 + wn * 64 + ni * 8 + 2 * (lane & 3);
                *(__half2*)(g_Hh + (size_t)r * HCOLS + c) =
                    __floats2half2_rn(acc[mt][ni][0] * coef, acc[mt][ni][1] * coef);
                *(__half2*)(g_Hh + (size_t)(r + 8) * HCOLS + c) =
                    __floats2half2_rn(acc[mt][ni][2] * coef, acc[mt][ni][3] * coef);
            }
        }
    }
}

// ---------------------------------------------------------------------------
// GEMM2: out[8192,12288]; per comp: out = Hh_comp @ Bh_comp^T
// Persistent CTAs over 64x96 = 6144 tiles.
// ---------------------------------------------------------------------------
__global__ void __launch_bounds__(128, 2)
tc_gemm2(float* __restrict__ out) {
    extern __shared__ __align__(16) char sm[];
    const int tid = threadIdx.x, lane = tid & 31, wid = tid >> 5;
    const int wm = wid & 1, wn = wid >> 1;
    const int NCT = OUTCOLS / 128;         // 96
    const int NTILE = NCT * (MTOT / 128);  // 6144

    #pragma unroll 1
    for (int tile = blockIdx.x; tile < NTILE; tile += gridDim.x) {
        const int row0 = (tile / NCT) * 128;
        const int col0 = (tile % NCT) * 128;
        const int comp = col0 >> 12;
        const int cl   = col0 & 4095;

        float acc[4][8][4];
        #pragma unroll
        for (int i = 0; i < 4; i++)
            #pragma unroll
            for (int j = 0; j < 8; j++)
                #pragma unroll
                for (int q = 0; q < 4; q++) acc[i][j][q] = 0.f;

        gemm_core<NR / 64>(g_Hh + (size_t)row0 * HCOLS + comp * NR, HCOLS,
                           g_Bh + (size_t)comp * DOUT * NR + (size_t)cl * NR, NR, sm, acc);
        __syncthreads();

        #pragma unroll
        for (int mt = 0; mt < 4; mt++) {
            #pragma unroll
            for (int ni = 0; ni < 8; ni++) {
                int r = row0 + wm * 64 + mt * 16 + (lane >> 2);
                int c = col0 + wn * 64 + ni * 8 + 2 * (lane & 3);
                *(float2*)(out + (size_t)r * OUTCOLS + c) =
                    make_float2(acc[mt][ni][0], acc[mt][ni][1]);
                *(float2*)(out + (size_t)(r + 8) * OUTCOLS + c) =
                    make_float2(acc[mt][ni][2], acc[mt][ni][3]);
            }
        }
    }
}

// ---------------------------------------------------------------------------
extern "C" void kernel_launch(void* const* d_in, const int* in_sizes, int n_in,
                              void* d_out, int out_size) {
    const float* x       = (const float*)d_in[0];
    const float* masks   = (const float*)d_in[2];
    const float* scaling = (const float*)d_in[3];
    const float* qA      = (const float*)d_in[4];
    const float* qB      = (const float*)d_in[5];
    const float* kA      = (const float*)d_in[6];
    const float* kB      = (const float*)d_in[7];
    const float* vA      = (const float*)d_in[8];
    const float* vB      = (const float*)d_in[9];
    float* out = (float*)d_out;

    const int SMEM = BSTAGES * STAGE_B;   // 98304 per CTA -> 2 CTAs/SM
    cudaFuncSetAttribute(tc_gemm1, cudaFuncAttributeMaxDynamicSharedMemorySize, SMEM);
    cudaFuncSetAttribute(tc_gemm2, cudaFuncAttributeMaxDynamicSharedMemorySize, SMEM);

    convx_k<<<(MTOT * DIN) / (512 * 8), 512>>>(x);
    transA_k<<<dim3(DIN / 32, RANK / 32, 24), dim3(32, 8)>>>(qA, kA, vA);
    transB_k<<<dim3(NR / 32, DOUT / 32, 3), dim3(32, 8)>>>(qB, kB, vB);

    const int GRID = 2 * 148;   // persistent, 2 CTAs per SM
    tc_gemm1<<<GRID, 128, SMEM>>>(masks, scaling);
    tc_gemm2<<<GRID, 128, SMEM>>>(out);
}